// round 10
// baseline (speedup 1.0000x reference)
#include <cuda_runtime.h>
#include <cuda_bf16.h>
#include <cstdint>

#define EPS  1e-6f
#define BB   512
#define KK   1024
#define DDIM 256

// ---------------- scratch (device globals: allocation-free) -----------------
__device__ __nv_bfloat16 g_xh[BB * DDIM], g_xl[BB * DDIM];
__device__ __nv_bfloat16 g_ph[KK * DDIM], g_pl[KK * DDIM];
__device__ __nv_bfloat16 g_ah[KK * DDIM], g_al[KK * DDIM];
__device__ float g_x2[BB], g_p2[KK], g_pa[KK], g_na2[KK];

// ---------------- helpers ----------------------------------------------------
__device__ __forceinline__ uint32_t smem_u32(const void* p) {
    uint32_t r;
    asm("{ .reg .u64 t; cvta.to.shared.u64 t, %1; cvt.u32.u64 %0, t; }"
        : "=r"(r) : "l"(p));
    return r;
}
__device__ __forceinline__ void ldsm_x4(uint32_t* r, uint32_t addr) {
    asm volatile("ldmatrix.sync.aligned.m8n8.x4.shared.b16 {%0,%1,%2,%3}, [%4];"
                 : "=r"(r[0]), "=r"(r[1]), "=r"(r[2]), "=r"(r[3]) : "r"(addr));
}
__device__ __forceinline__ void ldsm_x2(uint32_t* r, uint32_t addr) {
    asm volatile("ldmatrix.sync.aligned.m8n8.x2.shared.b16 {%0,%1}, [%2];"
                 : "=r"(r[0]), "=r"(r[1]) : "r"(addr));
}
__device__ __forceinline__ void mma_bf16(float* d, const uint32_t* a,
                                         uint32_t b0, uint32_t b1) {
    asm volatile(
        "mma.sync.aligned.m16n8k16.row.col.f32.bf16.bf16.f32 "
        "{%0,%1,%2,%3}, {%4,%5,%6,%7}, {%8,%9}, {%0,%1,%2,%3};"
        : "+f"(d[0]), "+f"(d[1]), "+f"(d[2]), "+f"(d[3])
        : "r"(a[0]), "r"(a[1]), "r"(a[2]), "r"(a[3]), "r"(b0), "r"(b1));
}
__device__ __forceinline__ void cp16(uint32_t dst, const void* src) {
    asm volatile("cp.async.cg.shared.global [%0], [%1], 16;"
                 :: "r"(dst), "l"(src) : "memory");
}
#define CP_COMMIT() asm volatile("cp.async.commit_group;" ::: "memory")
#define CP_WAIT(n)  asm volatile("cp.async.wait_group %0;" :: "n"(n) : "memory")

// ============================================================================
// Kernel 1: fp32 -> bf16 hi/lo splits + exact fp32 stats. One warp per row.
// ============================================================================
__device__ __forceinline__ uint32_t pack_hi(float f0, float f1,
                                            float& r0, float& r1) {
    __nv_bfloat16 h0 = __float2bfloat16_rn(f0);
    __nv_bfloat16 h1 = __float2bfloat16_rn(f1);
    r0 = f0 - __bfloat162float(h0);
    r1 = f1 - __bfloat162float(h1);
    return (uint32_t)__bfloat16_as_ushort(h0) |
           ((uint32_t)__bfloat16_as_ushort(h1) << 16);
}
__device__ __forceinline__ uint32_t pack_lo(float r0, float r1) {
    return (uint32_t)__bfloat16_as_ushort(__float2bfloat16_rn(r0)) |
           ((uint32_t)__bfloat16_as_ushort(__float2bfloat16_rn(r1)) << 16);
}
__device__ __forceinline__ void split8(const float* f, uint4& hi, uint4& lo) {
    float r[8];
    hi.x = pack_hi(f[0], f[1], r[0], r[1]);
    hi.y = pack_hi(f[2], f[3], r[2], r[3]);
    hi.z = pack_hi(f[4], f[5], r[4], r[5]);
    hi.w = pack_hi(f[6], f[7], r[6], r[7]);
    lo.x = pack_lo(r[0], r[1]); lo.y = pack_lo(r[2], r[3]);
    lo.z = pack_lo(r[4], r[5]); lo.w = pack_lo(r[6], r[7]);
}

__global__ __launch_bounds__(256)
void conv_stats_kernel(const float* __restrict__ x,
                       const float* __restrict__ p,
                       const float* __restrict__ a)
{
    const int w    = blockIdx.x * 8 + (threadIdx.x >> 5);
    const int lane = threadIdx.x & 31;
    if (w < BB) {
        const int r = w;
        float f[8];
        *(float4*)&f[0] = *(const float4*)(x + r * DDIM + lane * 8);
        *(float4*)&f[4] = *(const float4*)(x + r * DDIM + lane * 8 + 4);
        uint4 hi, lo;
        split8(f, hi, lo);
        *(uint4*)(g_xh + r * DDIM + lane * 8) = hi;
        *(uint4*)(g_xl + r * DDIM + lane * 8) = lo;
        float x2 = 0.f;
        #pragma unroll
        for (int i = 0; i < 8; i++) x2 += f[i] * f[i];
        #pragma unroll
        for (int m = 16; m; m >>= 1) x2 += __shfl_xor_sync(~0u, x2, m);
        if (lane == 0) g_x2[r] = x2;
    } else {
        const int r = w - BB;
        float fp[8], fa[8];
        *(float4*)&fp[0] = *(const float4*)(p + r * DDIM + lane * 8);
        *(float4*)&fp[4] = *(const float4*)(p + r * DDIM + lane * 8 + 4);
        *(float4*)&fa[0] = *(const float4*)(a + r * DDIM + lane * 8);
        *(float4*)&fa[4] = *(const float4*)(a + r * DDIM + lane * 8 + 4);
        uint4 hi, lo;
        split8(fp, hi, lo);
        *(uint4*)(g_ph + r * DDIM + lane * 8) = hi;
        *(uint4*)(g_pl + r * DDIM + lane * 8) = lo;
        split8(fa, hi, lo);
        *(uint4*)(g_ah + r * DDIM + lane * 8) = hi;
        *(uint4*)(g_al + r * DDIM + lane * 8) = lo;
        float p2 = 0.f, pa = 0.f, na2 = 0.f;
        #pragma unroll
        for (int i = 0; i < 8; i++) {
            p2 += fp[i] * fp[i]; pa += fp[i] * fa[i]; na2 += fa[i] * fa[i];
        }
        #pragma unroll
        for (int m = 16; m; m >>= 1) {
            p2  += __shfl_xor_sync(~0u, p2,  m);
            pa  += __shfl_xor_sync(~0u, pa,  m);
            na2 += __shfl_xor_sync(~0u, na2, m);
        }
        if (lane == 0) { g_p2[r] = p2; g_pa[r] = pa; g_na2[r] = na2; }
    }
}

// ============================================================================
// Kernel 2: dual split-GEMM (mma.sync bf16), HIGH-OCCUPANCY config.
//   CTA: 64(m) x 16(n), 8 warps 4x2, warp tile 16x8. ~4 CTAs/SM, 512 CTAs.
//   Stage = X(8K) + P(2K) + A(2K) = 12KB; 2 stages = 24KB.
//   Row layout: 128B = hi k32 (64B) | lo k32 (64B); swizzle: col ^ ((row&7)<<4).
// ============================================================================
#define MT    64
#define NT    16
#define KC    32
#define NCH   (DDIM / KC)   // 8
#define STAGE 12288
#define XOFF  0
#define POFF  8192
#define AOFF  10240
#define SMEM2 (2 * STAGE)   // 24576

__global__ __launch_bounds__(256, 4)
void hyp_hmma_kernel(float* __restrict__ out)
{
    extern __shared__ char smem[];
    const uint32_t smb = smem_u32(smem);

    const int tid  = threadIdx.x;
    const int wid  = tid >> 5;
    const int lane = tid & 31;
    const int k0   = blockIdx.x * NT;
    const int b0   = blockIdx.y * MT;

    // ---- cp.async loader: 3x 16B per thread per chunk -----------------------
    // X: 512 cp16 (2/thread); P/A: 256 cp16 (1/thread, tid>>6 selects array)
    const int xrow = tid >> 2, xseg = tid & 3;
    const __nv_bfloat16* xsrc_h = g_xh + (size_t)(b0 + xrow) * DDIM + xseg * 8;
    const __nv_bfloat16* xsrc_l = g_xl + (size_t)(b0 + xrow) * DDIM + xseg * 8;
    const uint32_t xdst_h = XOFF + xrow * 128 + ((xseg * 16)      ^ ((xrow & 7) << 4));
    const uint32_t xdst_l = XOFF + xrow * 128 + ((64 + xseg * 16) ^ ((xrow & 7) << 4));

    const int arr  = tid >> 6;            // 0:ph 1:pl 2:ah 3:al
    const int prow = (tid & 63) >> 2;     // 0..15
    const int pseg = tid & 3;
    const __nv_bfloat16* basrc =
        (arr == 0 ? g_ph : arr == 1 ? g_pl : arr == 2 ? g_ah : g_al)
        + (size_t)(k0 + prow) * DDIM + pseg * 8;
    const uint32_t badst = (arr >> 1 ? AOFF : POFF) + prow * 128
        + (((arr & 1) * 64 + pseg * 16) ^ ((prow & 7) << 4));

    auto load_chunk = [&](int stage, int c) {
        const int c0 = c * KC;
        const uint32_t sb = smb + stage * STAGE;
        cp16(sb + xdst_h, xsrc_h + c0);
        cp16(sb + xdst_l, xsrc_l + c0);
        cp16(sb + badst,  basrc + c0);
        CP_COMMIT();
    };

    // ---- warp tiling / ldsm addressing --------------------------------------
    const int wm = (wid >> 1) * 16;          // 4 m-warps
    const int wn = (wid & 1)  * 8;           // 2 n-warps
    // A (x4): m16k16 per kstep
    const int g  = lane >> 3;
    const int r  = lane & 7;
    const int rowadd = (g & 1) * 8 + r;
    const int cadd   = (g >> 1) * 16;        // bytes: k8 offset
    const uint32_t axor  = (rowadd & 7) << 4;
    const uint32_t xterm = XOFF + (wm + rowadd) * 128;
    const uint32_t aoff_h[2] = { (0u  + cadd) ^ axor, (32u + cadd) ^ axor };
    const uint32_t aoff_l[2] = { (64u + cadd) ^ axor, (96u + cadd) ^ axor };
    // B (x2): n8k16 per kstep; lanes 0-15 carry addresses
    const int brow = lane & 7;
    const int bsel = ((lane >> 3) & 1) * 16; // bytes: k8 offset
    const uint32_t bxor  = (brow & 7) << 4;
    const uint32_t pterm = POFF + (wn + brow) * 128;
    const uint32_t aterm = AOFF + (wn + brow) * 128;
    const uint32_t boff_h[2] = { (0u  + bsel) ^ bxor, (32u + bsel) ^ bxor };
    const uint32_t boff_l[2] = { (64u + bsel) ^ bxor, (96u + bsel) ^ bxor };

    float accP[4] = {}, accA[4] = {};

    load_chunk(0, 0);
    load_chunk(1, 1);

    for (int c = 0; c < NCH; c++) {
        if (c < NCH - 1) CP_WAIT(1); else CP_WAIT(0);
        __syncthreads();

        const uint32_t sb = smb + (c & 1) * STAGE;
        #pragma unroll
        for (int ks = 0; ks < 2; ks++) {
            uint32_t axh[4], axl[4], bph[2], bpl[2], bah[2], bal[2];
            ldsm_x4(axh, sb + xterm + aoff_h[ks]);
            ldsm_x4(axl, sb + xterm + aoff_l[ks]);
            ldsm_x2(bph, sb + pterm + boff_h[ks]);
            ldsm_x2(bpl, sb + pterm + boff_l[ks]);
            ldsm_x2(bah, sb + aterm + boff_h[ks]);
            ldsm_x2(bal, sb + aterm + boff_l[ks]);
            // xp += xh*ph + xl*ph + xh*pl   (ll dropped, ~2^-16 rel)
            mma_bf16(accP, axh, bph[0], bph[1]);
            mma_bf16(accA, axh, bah[0], bah[1]);
            mma_bf16(accP, axl, bph[0], bph[1]);
            mma_bf16(accA, axl, bah[0], bah[1]);
            mma_bf16(accP, axh, bpl[0], bpl[1]);
            mma_bf16(accA, axh, bal[0], bal[1]);
        }

        if (c + 2 < NCH) {
            __syncthreads();               // all warps done reading this stage
            load_chunk(c & 1, c + 2);      // refill it, async
        }
    }

    // ---- epilogue: hyperbolic MLR logit (stats straight from L2) ------------
    #pragma unroll
    for (int h = 0; h < 2; h++) {
        const int mloc = wm + h * 8 + (lane >> 2);
        const float x2 = g_x2[b0 + mloc];
        const int kloc = wn + (lane & 3) * 2;
        float2 res;
        float* rr = (float*)&res;
        #pragma unroll
        for (int q = 0; q < 2; q++) {
            const int kc2 = kloc + q;
            const float xp  = accP[h * 2 + q];
            const float xa  = accA[h * 2 + q];
            const float p2  = g_p2[k0 + kc2];
            const float pa  = g_pa[k0 + kc2];
            const float na2 = g_na2[k0 + kc2];

            float beta  = 1.f - p2;
            float alpha = -(1.f - 2.f * xp + x2);
            float den   = 1.f - 2.f * xp + p2 * x2 + EPS;
            float inv   = 1.f / den;
            float z2 = (alpha*alpha*p2 + 2.f*alpha*beta*xp + beta*beta*x2)
                       * inv * inv;
            float za = beta * (alpha * pa + beta * xa) * inv;
            float na = beta * sqrtf(na2);
            float lam = 2.f / (beta + EPS);
            float tt = 2.f * za / ((1.f - z2) * na + EPS);
            rr[q] = lam * na * asinhf(tt);
        }
        *(float2*)(out + (size_t)(b0 + mloc) * KK + k0 + kloc) = res;
    }
}

// ============================================================================
extern "C" void kernel_launch(void* const* d_in, const int* in_sizes, int n_in,
                              void* d_out, int out_size)
{
    const float* x = (const float*)d_in[0];
    const float* p = (const float*)d_in[1];
    const float* a = (const float*)d_in[2];
    float* out = (float*)d_out;

    conv_stats_kernel<<<(BB + KK) / 8, 256>>>(x, p, a);

    dim3 grid(KK / NT, BB / MT);    // (64, 8) = 512 CTAs, ~4/SM
    hyp_hmma_kernel<<<grid, 256, SMEM2>>>(out);   // 24KB dynamic smem
}

// round 11
// speedup vs baseline: 1.1711x; 1.1711x over previous
#include <cuda_runtime.h>
#include <cuda_fp16.h>
#include <cstdint>

#define EPS  1e-6f
#define BB   512
#define KK   1024
#define DDIM 256

// ---------------- scratch (device globals: allocation-free) -----------------
__device__ __half g_xh[BB * DDIM], g_xL[BB * DDIM];   // x hi, (x-hi)*4096
__device__ __half g_ph[KK * DDIM], g_ah[KK * DDIM];   // p hi, a hi
__device__ float g_x2[BB], g_p2[KK], g_pa[KK], g_na2[KK];

// ---------------- helpers ----------------------------------------------------
__device__ __forceinline__ uint32_t smem_u32(const void* p) {
    uint32_t r;
    asm("{ .reg .u64 t; cvta.to.shared.u64 t, %1; cvt.u32.u64 %0, t; }"
        : "=r"(r) : "l"(p));
    return r;
}
__device__ __forceinline__ void ldsm_x4(uint32_t* r, uint32_t addr) {
    asm volatile("ldmatrix.sync.aligned.m8n8.x4.shared.b16 {%0,%1,%2,%3}, [%4];"
                 : "=r"(r[0]), "=r"(r[1]), "=r"(r[2]), "=r"(r[3]) : "r"(addr));
}
__device__ __forceinline__ void ldsm_x2(uint32_t* r, uint32_t addr) {
    asm volatile("ldmatrix.sync.aligned.m8n8.x2.shared.b16 {%0,%1}, [%2];"
                 : "=r"(r[0]), "=r"(r[1]) : "r"(addr));
}
__device__ __forceinline__ void mma_f16(float* d, const uint32_t* a,
                                        uint32_t b0, uint32_t b1) {
    asm volatile(
        "mma.sync.aligned.m16n8k16.row.col.f32.f16.f16.f32 "
        "{%0,%1,%2,%3}, {%4,%5,%6,%7}, {%8,%9}, {%0,%1,%2,%3};"
        : "+f"(d[0]), "+f"(d[1]), "+f"(d[2]), "+f"(d[3])
        : "r"(a[0]), "r"(a[1]), "r"(a[2]), "r"(a[3]), "r"(b0), "r"(b1));
}
__device__ __forceinline__ void cp16(uint32_t dst, const void* src) {
    asm volatile("cp.async.cg.shared.global [%0], [%1], 16;"
                 :: "r"(dst), "l"(src) : "memory");
}
#define CP_COMMIT() asm volatile("cp.async.commit_group;" ::: "memory")
#define CP_WAIT(n)  asm volatile("cp.async.wait_group %0;" :: "n"(n) : "memory")

// ============================================================================
// Kernel 1: fp32 -> fp16 hi + scaled-lo (x only) + exact fp32 stats.
// ============================================================================
__device__ __forceinline__ uint32_t pack2h(__half a, __half b) {
    return (uint32_t)__half_as_ushort(a) | ((uint32_t)__half_as_ushort(b) << 16);
}

__global__ __launch_bounds__(256)
void conv_stats_kernel(const float* __restrict__ x,
                       const float* __restrict__ p,
                       const float* __restrict__ a)
{
    const int w    = blockIdx.x * 8 + (threadIdx.x >> 5);
    const int lane = threadIdx.x & 31;
    if (w < BB) {
        const int r = w;
        float f[8];
        *(float4*)&f[0] = *(const float4*)(x + r * DDIM + lane * 8);
        *(float4*)&f[4] = *(const float4*)(x + r * DDIM + lane * 8 + 4);
        uint4 hi, lo;
        uint32_t* hv = (uint32_t*)&hi;
        uint32_t* lv = (uint32_t*)&lo;
        float x2 = 0.f;
        #pragma unroll
        for (int i = 0; i < 4; i++) {
            __half h0 = __float2half_rn(f[2*i]);
            __half h1 = __float2half_rn(f[2*i+1]);
            float  l0 = (f[2*i]   - __half2float(h0)) * 4096.0f;
            float  l1 = (f[2*i+1] - __half2float(h1)) * 4096.0f;
            hv[i] = pack2h(h0, h1);
            lv[i] = pack2h(__float2half_rn(l0), __float2half_rn(l1));
            x2 += f[2*i]*f[2*i] + f[2*i+1]*f[2*i+1];
        }
        *(uint4*)(g_xh + r * DDIM + lane * 8) = hi;
        *(uint4*)(g_xL + r * DDIM + lane * 8) = lo;
        #pragma unroll
        for (int m = 16; m; m >>= 1) x2 += __shfl_xor_sync(~0u, x2, m);
        if (lane == 0) g_x2[r] = x2;
    } else {
        const int r = w - BB;
        float fp[8], fa[8];
        *(float4*)&fp[0] = *(const float4*)(p + r * DDIM + lane * 8);
        *(float4*)&fp[4] = *(const float4*)(p + r * DDIM + lane * 8 + 4);
        *(float4*)&fa[0] = *(const float4*)(a + r * DDIM + lane * 8);
        *(float4*)&fa[4] = *(const float4*)(a + r * DDIM + lane * 8 + 4);
        uint4 hp, ha;
        uint32_t* pv = (uint32_t*)&hp;
        uint32_t* av = (uint32_t*)&ha;
        float p2 = 0.f, pa = 0.f, na2 = 0.f;
        #pragma unroll
        for (int i = 0; i < 4; i++) {
            pv[i] = pack2h(__float2half_rn(fp[2*i]), __float2half_rn(fp[2*i+1]));
            av[i] = pack2h(__float2half_rn(fa[2*i]), __float2half_rn(fa[2*i+1]));
            p2  += fp[2*i]*fp[2*i] + fp[2*i+1]*fp[2*i+1];
            pa  += fp[2*i]*fa[2*i] + fp[2*i+1]*fa[2*i+1];
            na2 += fa[2*i]*fa[2*i] + fa[2*i+1]*fa[2*i+1];
        }
        *(uint4*)(g_ph + r * DDIM + lane * 8) = hp;
        *(uint4*)(g_ah + r * DDIM + lane * 8) = ha;
        #pragma unroll
        for (int m = 16; m; m >>= 1) {
            p2  += __shfl_xor_sync(~0u, p2,  m);
            pa  += __shfl_xor_sync(~0u, pa,  m);
            na2 += __shfl_xor_sync(~0u, na2, m);
        }
        if (lane == 0) { g_p2[r] = p2; g_pa[r] = pa; g_na2[r] = na2; }
    }
}

// ============================================================================
// Kernel 2: dual 2-term fp16 split-GEMM (mma.sync), cp.async 2-stage.
//   xp = accP1 + 2^-12 * accP2 where P1 = xh.ph, P2 = XL.ph (XL = xl*4096).
//   CTA: 64(m) x 16(n), 8 warps 4x2, warp tile 16x8.
//   Chunk KC=64 (128B rows); stage = Xh(8K)+XL(8K)+Ph(2K)+Ah(2K) = 20KB.
// ============================================================================
#define MT    64
#define NT    16
#define KC    64
#define NCH   (DDIM / KC)   // 4
#define XHOFF 0
#define XLOFF 8192
#define PHOFF 16384
#define AHOFF 18432
#define STAGE 20480
#define SMEM2 (2 * STAGE)   // 40960

__global__ __launch_bounds__(256)
void hyp_hmma_kernel(float* __restrict__ out)
{
    extern __shared__ char smem[];
    const uint32_t smb = smem_u32(smem);

    const int tid  = threadIdx.x;
    const int wid  = tid >> 5;
    const int lane = tid & 31;
    const int k0   = blockIdx.x * NT;
    const int b0   = blockIdx.y * MT;

    // ---- cp.async loader: 5x 16B per thread per chunk -----------------------
    // Xh/XL: 512 cp16 each (2/thread); Ph/Ah: 128 cp16 each (tid>>7 selects)
    const int xr0 = tid >> 3,            xs0 = tid & 7;          // idx = tid
    const int xr1 = (256 + tid) >> 3,    xs1 = tid & 7;          // idx = 256+tid
    const __half* xh0 = g_xh + (size_t)(b0 + xr0) * DDIM + xs0 * 8;
    const __half* xh1 = g_xh + (size_t)(b0 + xr1) * DDIM + xs1 * 8;
    const __half* xl0 = g_xL + (size_t)(b0 + xr0) * DDIM + xs0 * 8;
    const __half* xl1 = g_xL + (size_t)(b0 + xr1) * DDIM + xs1 * 8;
    const uint32_t xd0 = xr0 * 128 + ((xs0 * 16) ^ ((xr0 & 7) << 4));
    const uint32_t xd1 = xr1 * 128 + ((xs1 * 16) ^ ((xr1 & 7) << 4));

    const int arr  = tid >> 7;            // 0: ph, 1: ah
    const int prow = (tid & 127) >> 3;    // 0..15
    const int pseg = tid & 7;
    const __half* basrc = (arr ? g_ah : g_ph) + (size_t)(k0 + prow) * DDIM + pseg * 8;
    const uint32_t badst = (arr ? AHOFF : PHOFF) + prow * 128
        + ((pseg * 16) ^ ((prow & 7) << 4));

    auto load_chunk = [&](int stage, int c) {
        const int c0 = c * KC;
        const uint32_t sb = smb + stage * STAGE;
        cp16(sb + XHOFF + xd0, xh0 + c0);
        cp16(sb + XHOFF + xd1, xh1 + c0);
        cp16(sb + XLOFF + xd0, xl0 + c0);
        cp16(sb + XLOFF + xd1, xl1 + c0);
        cp16(sb + badst,       basrc + c0);
        CP_COMMIT();
    };

    // ---- warp tiling / ldsm addressing --------------------------------------
    const int wm = (wid >> 1) * 16;          // 4 m-warps
    const int wn = (wid & 1)  * 8;           // 2 n-warps
    // A (x4): m16k16 per kstep
    const int g  = lane >> 3;
    const int r  = lane & 7;
    const int rowadd = (g & 1) * 8 + r;
    const int cadd   = (g >> 1) * 16;        // k8 byte offset
    const uint32_t axor  = (rowadd & 7) << 4;
    const uint32_t xterm = (wm + rowadd) * 128;
    // B (x2): n8k16 per kstep
    const int brow = lane & 7;
    const int bsel = ((lane >> 3) & 1) * 16;
    const uint32_t bxor  = (brow & 7) << 4;
    const uint32_t pterm = PHOFF + (wn + brow) * 128;
    const uint32_t aterm = AHOFF + (wn + brow) * 128;

    float accP1[4] = {}, accP2[4] = {}, accA1[4] = {}, accA2[4] = {};

    load_chunk(0, 0);
    load_chunk(1, 1);

    for (int c = 0; c < NCH; c++) {
        if (c < NCH - 1) CP_WAIT(1); else CP_WAIT(0);
        __syncthreads();

        const uint32_t sb = smb + (c & 1) * STAGE;
        #pragma unroll
        for (int ks = 0; ks < 4; ks++) {
            const uint32_t akoff = (uint32_t)(32 * ks + cadd) ^ axor;
            const uint32_t bkoff = (uint32_t)(32 * ks + bsel) ^ bxor;
            uint32_t axh[4], axl[4], bp[2], ba[2];
            ldsm_x4(axh, sb + XHOFF + xterm + akoff);
            ldsm_x4(axl, sb + XLOFF + xterm + akoff);
            ldsm_x2(bp,  sb + pterm + bkoff);
            ldsm_x2(ba,  sb + aterm + bkoff);
            mma_f16(accP1, axh, bp[0], bp[1]);
            mma_f16(accA1, axh, ba[0], ba[1]);
            mma_f16(accP2, axl, bp[0], bp[1]);
            mma_f16(accA2, axl, ba[0], ba[1]);
        }

        if (c + 2 < NCH) {
            __syncthreads();               // all warps done reading this stage
            load_chunk(c & 1, c + 2);
        }
    }

    // ---- epilogue: combine splits + hyperbolic MLR logit ---------------------
    const float S = 1.0f / 4096.0f;   // 2^-12
    #pragma unroll
    for (int h = 0; h < 2; h++) {
        const int mloc = wm + h * 8 + (lane >> 2);
        const float x2 = g_x2[b0 + mloc];
        const int kloc = wn + (lane & 3) * 2;
        float2 res;
        float* rr = (float*)&res;
        #pragma unroll
        for (int q = 0; q < 2; q++) {
            const int kc2 = kloc + q;
            const float xp  = accP1[h * 2 + q] + S * accP2[h * 2 + q];
            const float xa  = accA1[h * 2 + q] + S * accA2[h * 2 + q];
            const float p2  = g_p2[k0 + kc2];
            const float pa  = g_pa[k0 + kc2];
            const float na2 = g_na2[k0 + kc2];

            float beta  = 1.f - p2;
            float alpha = -(1.f - 2.f * xp + x2);
            float den   = 1.f - 2.f * xp + p2 * x2 + EPS;
            float inv   = 1.f / den;
            float z2 = (alpha*alpha*p2 + 2.f*alpha*beta*xp + beta*beta*x2)
                       * inv * inv;
            float za = beta * (alpha * pa + beta * xa) * inv;
            float na = beta * sqrtf(na2);
            float lam = 2.f / (beta + EPS);
            float tt = 2.f * za / ((1.f - z2) * na + EPS);
            rr[q] = lam * na * asinhf(tt);
        }
        *(float2*)(out + (size_t)(b0 + mloc) * KK + k0 + kloc) = res;
    }
}

// ============================================================================
extern "C" void kernel_launch(void* const* d_in, const int* in_sizes, int n_in,
                              void* d_out, int out_size)
{
    const float* x = (const float*)d_in[0];
    const float* p = (const float*)d_in[1];
    const float* a = (const float*)d_in[2];
    float* out = (float*)d_out;

    conv_stats_kernel<<<(BB + KK) / 8, 256>>>(x, p, a);

    dim3 grid(KK / NT, BB / MT);    // (64, 8) = 512 CTAs
    hyp_hmma_kernel<<<grid, 256, SMEM2>>>(out);   // 40KB dynamic smem
}

// round 12
// speedup vs baseline: 1.2917x; 1.1029x over previous
#include <cuda_runtime.h>
#include <cuda_fp16.h>
#include <cstdint>

#define EPS  1e-6f
#define BB   512
#define KK   1024
#define DDIM 256

// ---------------- scratch (device globals: allocation-free) -----------------
__device__ __half g_xh[BB * DDIM];                    // fp16(x)
__device__ __half g_ph[KK * DDIM], g_ah[KK * DDIM];   // fp16(p), fp16(a)
__device__ float g_x2[BB], g_p2[KK], g_pa[KK], g_na2[KK];

// ---------------- helpers ----------------------------------------------------
__device__ __forceinline__ uint32_t smem_u32(const void* p) {
    uint32_t r;
    asm("{ .reg .u64 t; cvta.to.shared.u64 t, %1; cvt.u32.u64 %0, t; }"
        : "=r"(r) : "l"(p));
    return r;
}
__device__ __forceinline__ void ldsm_x4(uint32_t* r, uint32_t addr) {
    asm volatile("ldmatrix.sync.aligned.m8n8.x4.shared.b16 {%0,%1,%2,%3}, [%4];"
                 : "=r"(r[0]), "=r"(r[1]), "=r"(r[2]), "=r"(r[3]) : "r"(addr));
}
__device__ __forceinline__ void mma_f16(float* d, const uint32_t* a,
                                        uint32_t b0, uint32_t b1) {
    asm volatile(
        "mma.sync.aligned.m16n8k16.row.col.f32.f16.f16.f32 "
        "{%0,%1,%2,%3}, {%4,%5,%6,%7}, {%8,%9}, {%0,%1,%2,%3};"
        : "+f"(d[0]), "+f"(d[1]), "+f"(d[2]), "+f"(d[3])
        : "r"(a[0]), "r"(a[1]), "r"(a[2]), "r"(a[3]), "r"(b0), "r"(b1));
}
__device__ __forceinline__ void cp16(uint32_t dst, const void* src) {
    asm volatile("cp.async.cg.shared.global [%0], [%1], 16;"
                 :: "r"(dst), "l"(src) : "memory");
}
#define CP_COMMIT() asm volatile("cp.async.commit_group;" ::: "memory")
#define CP_WAIT(n)  asm volatile("cp.async.wait_group %0;" :: "n"(n) : "memory")

// ============================================================================
// Kernel 1: fp32 -> fp16 conversion + exact fp32 stats. One warp per row.
// ============================================================================
__device__ __forceinline__ uint32_t pack2h(float a, float b) {
    __half2 h = __floats2half2_rn(a, b);
    return *(uint32_t*)&h;
}

__global__ __launch_bounds__(256)
void conv_stats_kernel(const float* __restrict__ x,
                       const float* __restrict__ p,
                       const float* __restrict__ a)
{
    const int w    = blockIdx.x * 8 + (threadIdx.x >> 5);
    const int lane = threadIdx.x & 31;
    if (w < BB) {
        const int r = w;
        float f[8];
        *(float4*)&f[0] = *(const float4*)(x + r * DDIM + lane * 8);
        *(float4*)&f[4] = *(const float4*)(x + r * DDIM + lane * 8 + 4);
        uint4 hi;
        uint32_t* hv = (uint32_t*)&hi;
        float x2 = 0.f;
        #pragma unroll
        for (int i = 0; i < 4; i++) {
            hv[i] = pack2h(f[2*i], f[2*i+1]);
            x2 += f[2*i]*f[2*i] + f[2*i+1]*f[2*i+1];
        }
        *(uint4*)(g_xh + r * DDIM + lane * 8) = hi;
        #pragma unroll
        for (int m = 16; m; m >>= 1) x2 += __shfl_xor_sync(~0u, x2, m);
        if (lane == 0) g_x2[r] = x2;
    } else {
        const int r = w - BB;
        float fp[8], fa[8];
        *(float4*)&fp[0] = *(const float4*)(p + r * DDIM + lane * 8);
        *(float4*)&fp[4] = *(const float4*)(p + r * DDIM + lane * 8 + 4);
        *(float4*)&fa[0] = *(const float4*)(a + r * DDIM + lane * 8);
        *(float4*)&fa[4] = *(const float4*)(a + r * DDIM + lane * 8 + 4);
        uint4 hp, ha;
        uint32_t* pv = (uint32_t*)&hp;
        uint32_t* av = (uint32_t*)&ha;
        float p2 = 0.f, pa = 0.f, na2 = 0.f;
        #pragma unroll
        for (int i = 0; i < 4; i++) {
            pv[i] = pack2h(fp[2*i], fp[2*i+1]);
            av[i] = pack2h(fa[2*i], fa[2*i+1]);
            p2  += fp[2*i]*fp[2*i] + fp[2*i+1]*fp[2*i+1];
            pa  += fp[2*i]*fa[2*i] + fp[2*i+1]*fa[2*i+1];
            na2 += fa[2*i]*fa[2*i] + fa[2*i+1]*fa[2*i+1];
        }
        *(uint4*)(g_ph + r * DDIM + lane * 8) = hp;
        *(uint4*)(g_ah + r * DDIM + lane * 8) = ha;
        #pragma unroll
        for (int m = 16; m; m >>= 1) {
            p2  += __shfl_xor_sync(~0u, p2,  m);
            pa  += __shfl_xor_sync(~0u, pa,  m);
            na2 += __shfl_xor_sync(~0u, na2, m);
        }
        if (lane == 0) { g_p2[r] = p2; g_pa[r] = pa; g_na2[r] = na2; }
    }
}

// ============================================================================
// Kernel 2: dual fp16 GEMM (mma.sync), single term, cp.async 2-stage.
//   CTA: 64(m) x 16(n), 8 warps 4x2, warp tile 16x8. 512 CTAs.
//   Chunk KC=64; stage = Xh(8K) + Ph(2K) + Ah(2K) = 12KB; 2 stages = 24KB.
//   P and A b-fragments fetched with ONE ldmatrix.x4 (mat 0-1 = p, 2-3 = a).
//   Epilogue stats prefetched to regs before the mainloop.
// ============================================================================
#define MT    64
#define NT    16
#define KC    64
#define NCH   (DDIM / KC)   // 4
#define XHOFF 0
#define PHOFF 8192
#define AHOFF 10240
#define STAGE 12288
#define SMEM2 (2 * STAGE)   // 24576

__global__ __launch_bounds__(256)
void hyp_hmma_kernel(float* __restrict__ out)
{
    extern __shared__ char smem[];
    const uint32_t smb = smem_u32(smem);

    const int tid  = threadIdx.x;
    const int wid  = tid >> 5;
    const int lane = tid & 31;
    const int k0   = blockIdx.x * NT;
    const int b0   = blockIdx.y * MT;

    // ---- warp tiling ---------------------------------------------------------
    const int wm = (wid >> 1) * 16;          // 4 m-warps
    const int wn = (wid & 1)  * 8;           // 2 n-warps

    // ---- prefetch epilogue stats into regs (hidden under GEMM) --------------
    const int m0 = wm + (lane >> 2);         // h=0 row
    const int kc0 = k0 + wn + (lane & 3) * 2;
    float x2v[2], p2v[2], pav[2], na2v[2];
    x2v[0] = g_x2[b0 + m0];
    x2v[1] = g_x2[b0 + m0 + 8];
    p2v[0] = g_p2[kc0];  p2v[1] = g_p2[kc0 + 1];
    pav[0] = g_pa[kc0];  pav[1] = g_pa[kc0 + 1];
    na2v[0] = g_na2[kc0]; na2v[1] = g_na2[kc0 + 1];

    // ---- cp.async loader: 3x 16B per thread per chunk ------------------------
    const int xr0 = tid >> 3,         xs0 = tid & 7;   // idx = tid
    const int xr1 = (256 + tid) >> 3, xs1 = tid & 7;   // idx = 256 + tid
    const __half* xh0 = g_xh + (size_t)(b0 + xr0) * DDIM + xs0 * 8;
    const __half* xh1 = g_xh + (size_t)(b0 + xr1) * DDIM + xs1 * 8;
    const uint32_t xd0 = XHOFF + xr0 * 128 + ((xs0 * 16) ^ ((xr0 & 7) << 4));
    const uint32_t xd1 = XHOFF + xr1 * 128 + ((xs1 * 16) ^ ((xr1 & 7) << 4));

    const int arr  = tid >> 7;            // 0: ph, 1: ah
    const int prow = (tid & 127) >> 3;    // 0..15
    const int pseg = tid & 7;
    const __half* basrc = (arr ? g_ah : g_ph) + (size_t)(k0 + prow) * DDIM + pseg * 8;
    const uint32_t badst = (arr ? AHOFF : PHOFF) + prow * 128
        + ((pseg * 16) ^ ((prow & 7) << 4));

    auto load_chunk = [&](int stage, int c) {
        const int c0 = c * KC;
        const uint32_t sb = smb + stage * STAGE;
        cp16(sb + xd0,   xh0 + c0);
        cp16(sb + xd1,   xh1 + c0);
        cp16(sb + badst, basrc + c0);
        CP_COMMIT();
    };

    // ---- ldsm addressing ------------------------------------------------------
    // A (x4): m16k16 per kstep
    const int g  = lane >> 3;
    const int r  = lane & 7;
    const int rowadd = (g & 1) * 8 + r;
    const int cadd   = (g >> 1) * 16;        // k8 byte offset
    const uint32_t axor  = (rowadd & 7) << 4;
    const uint32_t xterm = XHOFF + (wm + rowadd) * 128;
    // B combined (x4): mat0-1 = p (k0-7, k8-15), mat2-3 = a
    const int brow = lane & 7;
    const uint32_t bko  = (uint32_t)(g & 1) * 16;       // k8 select
    const uint32_t bxor = (uint32_t)brow << 4;
    const uint32_t bterm = PHOFF + (uint32_t)(g >> 1) * (AHOFF - PHOFF)
                         + (wn + brow) * 128;

    float accP[4] = {}, accA[4] = {};

    load_chunk(0, 0);
    load_chunk(1, 1);

    for (int c = 0; c < NCH; c++) {
        if (c < NCH - 1) CP_WAIT(1); else CP_WAIT(0);
        __syncthreads();

        const uint32_t sb = smb + (c & 1) * STAGE;
        #pragma unroll
        for (int ks = 0; ks < 4; ks++) {
            uint32_t axh[4], bpa[4];
            ldsm_x4(axh, sb + xterm + ((uint32_t)(32 * ks + cadd) ^ axor));
            ldsm_x4(bpa, sb + bterm + ((uint32_t)(32 * ks) + bko ^ bxor));
            mma_f16(accP, axh, bpa[0], bpa[1]);
            mma_f16(accA, axh, bpa[2], bpa[3]);
        }

        if (c + 2 < NCH) {
            __syncthreads();               // all warps done reading this stage
            load_chunk(c & 1, c + 2);
        }
    }

    // ---- epilogue: hyperbolic MLR logit (stats already in regs) --------------
    #pragma unroll
    for (int h = 0; h < 2; h++) {
        const int mloc = wm + h * 8 + (lane >> 2);
        const float x2 = x2v[h];
        const int kloc = wn + (lane & 3) * 2;
        float2 res;
        float* rr = (float*)&res;
        #pragma unroll
        for (int q = 0; q < 2; q++) {
            const float xp  = accP[h * 2 + q];
            const float xa  = accA[h * 2 + q];
            const float p2  = p2v[q];
            const float pa  = pav[q];
            const float na2 = na2v[q];

            float beta  = 1.f - p2;
            float alpha = -(1.f - 2.f * xp + x2);
            float den   = 1.f - 2.f * xp + p2 * x2 + EPS;
            float inv   = 1.f / den;
            float z2 = (alpha*alpha*p2 + 2.f*alpha*beta*xp + beta*beta*x2)
                       * inv * inv;
            float za = beta * (alpha * pa + beta * xa) * inv;
            float na = beta * sqrtf(na2);
            float lam = 2.f / (beta + EPS);
            float tt = 2.f * za / ((1.f - z2) * na + EPS);
            rr[q] = lam * na * asinhf(tt);
        }
        *(float2*)(out + (size_t)(b0 + mloc) * KK + k0 + kloc) = res;
    }
}

// ============================================================================
extern "C" void kernel_launch(void* const* d_in, const int* in_sizes, int n_in,
                              void* d_out, int out_size)
{
    const float* x = (const float*)d_in[0];
    const float* p = (const float*)d_in[1];
    const float* a = (const float*)d_in[2];
    float* out = (float*)d_out;

    conv_stats_kernel<<<(BB + KK) / 8, 256>>>(x, p, a);

    dim3 grid(KK / NT, BB / MT);    // (64, 8) = 512 CTAs
    hyp_hmma_kernel<<<grid, 256, SMEM2>>>(out);   // 24KB dynamic smem
}